// round 15
// baseline (speedup 1.0000x reference)
#include <cuda_runtime.h>
#include <cstdint>

#define BATCH    4096
#define IN_FEAT  4096
#define NPAIRS_TOTAL 767   // 256 + 255 + 256
#define GT_STRIDE 68       // padded [16][68] gate tiles (bank-conflict-free)
#define GT_PAIR   (16 * GT_STRIDE)

// ---------------- scratch (device globals; no allocation allowed) ----------------
__device__ float g_h[(size_t)BATCH * IN_FEAT];              // 64 MB intermediate h
__device__ float g_gthi[(size_t)NPAIRS_TOTAL * GT_PAIR];    // gates^T hi (tf32-exact)
__device__ float g_gtlo[(size_t)NPAIRS_TOTAL * GT_PAIR];    // gates^T lo residual

// ---------------- tf32 helpers ----------------
__device__ __forceinline__ uint32_t tf32_hi(float x) {
    uint32_t h; asm("cvt.rna.tf32.f32 %0, %1;" : "=r"(h) : "f"(x)); return h;
}
// D += A(tf32) * B(tf32), m16n8k8, A row-major, B col-major
__device__ __forceinline__ void mma8(float* d, const uint32_t* a, const uint32_t* b) {
    asm volatile(
        "mma.sync.aligned.m16n8k8.row.col.f32.tf32.tf32.f32 "
        "{%0,%1,%2,%3}, {%4,%5,%6,%7}, {%8,%9}, {%0,%1,%2,%3};"
        : "+f"(d[0]), "+f"(d[1]), "+f"(d[2]), "+f"(d[3])
        : "r"(a[0]), "r"(a[1]), "r"(a[2]), "r"(a[3]), "r"(b[0]), "r"(b[1]));
}

// ---------------- gate reduction: emit transposed hi/lo tiles ----------------
__device__ __forceinline__ void store_gt(int gb, int o, float s1, float s2) {
    float* dh = g_gthi + (size_t)gb * GT_PAIR;
    float* dl = g_gtlo + (size_t)gb * GT_PAIR;
    int ij = o >> 3, m = o & 7;
    float h1 = __uint_as_float(tf32_hi(s1));
    dh[m * GT_STRIDE + ij] = h1;  dl[m * GT_STRIDE + ij] = s1 - h1;
    float h2 = __uint_as_float(tf32_hi(s2));
    dh[(8 + m) * GT_STRIDE + ij] = h2;  dl[(8 + m) * GT_STRIDE + ij] = s2 - h2;
}

__device__ __forceinline__ void reduce_one_pair_256(int gb, const float* __restrict__ src,
                                                    float* __restrict__ sG)
{
    int tid = threadIdx.x;
    float acc[16];
#pragma unroll
    for (int t = 0; t < 16; t++) acc[t] = 0.f;
#pragma unroll
    for (int rc = 0; rc < 16; rc++) {
        const float* p = src + rc * 4096;
#pragma unroll
        for (int t = 0; t < 16; t++) acc[t] += p[t * 256 + tid];
    }
#pragma unroll
    for (int t = 0; t < 16; t++) sG[t * 256 + tid] = acc[t];
    __syncthreads();
#pragma unroll
    for (int u = 0; u < 2; u++) {
        int o = u * 256 + tid;          // 0..511
        float s1 = 0.f;
#pragma unroll
        for (int n = 0; n < 8; n++) s1 += sG[o * 8 + n];
        int ij = o >> 3, nn = o & 7;
        float s2 = 0.f;
#pragma unroll
        for (int m = 0; m < 8; m++) s2 += sG[ij * 64 + m * 8 + nn];
        store_gt(gb, o, s1, s2);
    }
}

__device__ __forceinline__ void reduce_one_pair_128(int gb, const float* __restrict__ src,
                                                    float* __restrict__ sG)
{
    int tid = threadIdx.x;
#pragma unroll 1
    for (int half = 0; half < 2; half++) {
        float acc[16];
#pragma unroll
        for (int t = 0; t < 16; t++) acc[t] = 0.f;
#pragma unroll 4
        for (int rc = 0; rc < 16; rc++) {
            const float* p = src + rc * 4096 + half * 2048;
#pragma unroll
            for (int t = 0; t < 16; t++) acc[t] += p[t * 128 + tid];
        }
#pragma unroll
        for (int t = 0; t < 16; t++) sG[half * 2048 + t * 128 + tid] = acc[t];
    }
    __syncthreads();
#pragma unroll
    for (int u = 0; u < 4; u++) {
        int o = u * 128 + tid;          // 0..511
        float s1 = 0.f;
#pragma unroll
        for (int n = 0; n < 8; n++) s1 += sG[o * 8 + n];
        int ij = o >> 3, nn = o & 7;
        float s2 = 0.f;
#pragma unroll
        for (int m = 0; m < 8; m++) s2 += sG[ij * 64 + m * 8 + nn];
        store_gt(gb, o, s1, s2);
    }
}

// ---------------- Prep kernel: gates0 reduction + permuted gather ----------------
__global__ __launch_bounds__(256) void prep_kernel(
    const float* __restrict__ g0,
    const float* __restrict__ x, const int* __restrict__ perm)
{
    __shared__ float sG[4096];
    if (blockIdx.x < 256) {
        reduce_one_pair_256(blockIdx.x, g0 + (size_t)blockIdx.x * 65536, sG);
        return;
    }
    int b = blockIdx.x - 256;
    const float* xr = x + (size_t)b * IN_FEAT;
    float* hr = g_h + (size_t)b * IN_FEAT;
    int tid = threadIdx.x;
#pragma unroll
    for (int c = 0; c < 16; c++) {
        int q = c * 256 + tid;
        hr[q] = xr[perm[q]];
    }
}

// ---------------- Layer kernel: per-pair GEMM on tensor cores ----------------
// R13 binder: fragment loads were 4-lane-redundant LDG (8 strided rows per
// instr = 8 wavefronts; 64 wavefronts/iter vs 48 HMMA). Fix: stage each
// warp's 16x16 h tile via 2 COALESCED LDG.128 (lane->row t>>2, quarter t&3;
// 16 wavefronts), STS to pad-20 SMEM, then fragment reads are cheap LDS
// (x1: 2x LDS.128 broadcast; x2: LDS.32 at g*20+8+tg -- distinct banks
// mod 32, conflict-free). Warp-private region, __syncwarp only.
// Math identical to R13 (validated): 3-term tf32 split mma m16n8k8.
template<int OFFSET, bool EPI, bool FUSE_REDUCE>
__global__ __launch_bounds__(128, 4) void layer_kernel(
    int gate_base,
    const float* __restrict__ g1r, const float* __restrict__ g2r,
    const float* __restrict__ alphap,
    const float* __restrict__ scale,
    const float* __restrict__ bias,
    float* __restrict__ out)
{
    __shared__ float sS[4096];   // 16KB: reduce area / 4 x 320-float warp tiles

    int kx = blockIdx.x;
    if (FUSE_REDUCE) {
        if (kx < 511) {
            if (blockIdx.y == 0) {
                int gb = 256 + kx;
                const float* src = (gb < 511) ? g1r + (size_t)(gb - 256) * 65536
                                              : g2r + (size_t)(gb - 511) * 65536;
                reduce_one_pair_128(gb, src, sS);
            }
            return;
        }
        kx -= 511;
    }
    const int k = kx;
    const int tid = threadIdx.x;
    const int w = tid >> 5, t = tid & 31;
    const int g = t >> 2, tg = t & 3;
    const size_t col = ((size_t)(OFFSET + 2 * k)) * 8;   // 16 contiguous h columns
    float* sW = sS + w * 320;                            // warp-private 16x20 tile

    // ---- B fragments for this pair: held in registers for the whole job ----
    const float* bh = g_gthi + (size_t)(gate_base + k) * GT_PAIR;
    const float* bl = g_gtlo + (size_t)(gate_base + k) * GT_PAIR;
    uint32_t bhi[2][8][2], blo[2][8][2];
#pragma unroll
    for (int nb = 0; nb < 2; nb++)
#pragma unroll
        for (int kc = 0; kc < 8; kc++) {
            int idx = (nb * 8 + g) * GT_STRIDE + kc * 8 + tg;
            bhi[nb][kc][0] = __float_as_uint(__ldg(bh + idx));
            bhi[nb][kc][1] = __float_as_uint(__ldg(bh + idx + 4));
            blo[nb][kc][0] = __float_as_uint(__ldg(bl + idx));
            blo[nb][kc][1] = __float_as_uint(__ldg(bl + idx + 4));
        }

    float al = 1.f;
    float sc[2][2], bi[2][2];
    if (EPI) {
        al = __ldg(alphap);
#pragma unroll
        for (int nb = 0; nb < 2; nb++)
#pragma unroll
            for (int e = 0; e < 2; e++) {
                size_t c = col + nb * 8 + 2 * tg + e;
                sc[nb][e] = __ldg(scale + c);
                bi[nb][e] = __ldg(bias + c);
            }
    }

#pragma unroll 1
    for (int it = 0; it < 4; it++) {
        int rbase = blockIdx.y * 256 + it * 64 + w * 16;

        // ---- coalesced stage: 16 rows x 16 floats -> SMEM (pad 20) ----
#pragma unroll
        for (int hh = 0; hh < 2; hh++) {
            int row = (t >> 2) + hh * 8;
            float4 v = *(const float4*)(g_h + (size_t)(rbase + row) * IN_FEAT + col + (t & 3) * 4);
            *(float4*)(sW + row * 20 + (t & 3) * 4) = v;
        }
        __syncwarp();

        // ---- fragment reads from SMEM ----
        float4 u0 = *(const float4*)(sW + g * 20);
        float4 u1 = *(const float4*)(sW + g * 20 + 4);
        float4 v0 = *(const float4*)(sW + (g + 8) * 20);
        float4 v1 = *(const float4*)(sW + (g + 8) * 20 + 4);
        float x1a[8] = {u0.x, u0.y, u0.z, u0.w, u1.x, u1.y, u1.z, u1.w};
        float x1b[8] = {v0.x, v0.y, v0.z, v0.w, v1.x, v1.y, v1.z, v1.w};
        float x2a0 = sW[g * 20 + 8 + tg],        x2a1 = sW[g * 20 + 12 + tg];
        float x2b0 = sW[(g + 8) * 20 + 8 + tg],  x2b1 = sW[(g + 8) * 20 + 12 + tg];
        __syncwarp();   // reads done before next iter overwrites sW

        float d0[4] = {0.f, 0.f, 0.f, 0.f};
        float d1[4] = {0.f, 0.f, 0.f, 0.f};

#pragma unroll
        for (int kc = 0; kc < 8; kc++) {
            // A fragment (row-major m16k8): a0:(g,tg) a1:(g+8,tg) a2:(g,tg+4) a3:(g+8,tg+4)
            float av[4] = { x1a[kc] * x2a0, x1b[kc] * x2b0,
                            x1a[kc] * x2a1, x1b[kc] * x2b1 };
            uint32_t ah[4], alo_[4];
#pragma unroll
            for (int e = 0; e < 4; e++) {
                ah[e] = tf32_hi(av[e]);
                alo_[e] = __float_as_uint(av[e] - __uint_as_float(ah[e]));
            }
            mma8(d0, ah,   bhi[0][kc]);
            mma8(d0, ah,   blo[0][kc]);
            mma8(d0, alo_, bhi[0][kc]);
            mma8(d1, ah,   bhi[1][kc]);
            mma8(d1, ah,   blo[1][kc]);
            mma8(d1, alo_, bhi[1][kc]);
        }

        // D fragment: d0,d1 = row g cols 2tg,2tg+1 ; d2,d3 = row g+8 same cols
        int ra = rbase + g, rb = rbase + g + 8;
#pragma unroll
        for (int nb = 0; nb < 2; nb++) {
            float* d = nb ? d1 : d0;
            size_t ca = (size_t)ra * IN_FEAT + col + nb * 8 + 2 * tg;
            size_t cb = (size_t)rb * IN_FEAT + col + nb * 8 + 2 * tg;
            if (!EPI) {
                *(float2*)(g_h + ca) = make_float2(d[0], d[1]);
                *(float2*)(g_h + cb) = make_float2(d[2], d[3]);
            } else {
                *(float2*)(out + ca) = make_float2(al * d[0] * sc[nb][0] + bi[nb][0],
                                                   al * d[1] * sc[nb][1] + bi[nb][1]);
                *(float2*)(out + cb) = make_float2(al * d[2] * sc[nb][0] + bi[nb][0],
                                                   al * d[3] * sc[nb][1] + bi[nb][1]);
            }
        }
    }
}

// ---------------- launch ----------------
extern "C" void kernel_launch(void* const* d_in, const int* in_sizes, int n_in,
                              void* d_out, int out_size)
{
    (void)in_sizes; (void)n_in; (void)out_size;
    const float* x     = (const float*)d_in[0];
    const float* g0    = (const float*)d_in[1];
    const float* g1    = (const float*)d_in[2];
    const float* g2    = (const float*)d_in[3];
    const float* alpha = (const float*)d_in[4];
    const float* scale = (const float*)d_in[5];
    const float* bias  = (const float*)d_in[6];
    const int*   perm  = (const int*)d_in[7];
    float* out = (float*)d_out;

    // prep: gates0 reduce (256 blocks) + permuted gather (4096 blocks)
    prep_kernel<<<256 + BATCH, 256>>>(g0, x, perm);
    // layer 0: 511 leading reduce blocks (gates1+gates2) + 256 pair-blocks x 16 row-groups
    layer_kernel<0, false, true ><<<dim3(511 + 256, 16), 128>>>(0,   g1, g2, nullptr, nullptr, nullptr, nullptr);
    layer_kernel<1, false, false><<<dim3(255, 16),       128>>>(256, nullptr, nullptr, nullptr, nullptr, nullptr, nullptr);
    layer_kernel<0, true,  false><<<dim3(256, 16),       128>>>(511, nullptr, nullptr, alpha, scale, bias, out);
}

// round 16
// speedup vs baseline: 1.0234x; 1.0234x over previous
#include <cuda_runtime.h>
#include <cstdint>

#define BATCH    4096
#define IN_FEAT  4096
#define NPAIRS_TOTAL 767   // 256 + 255 + 256
#define GT_STRIDE 68       // padded [16][68] gate tiles (bank-conflict-free)
#define GT_PAIR   (16 * GT_STRIDE)

// ---------------- scratch (device globals; no allocation allowed) ----------------
__device__ float g_h[(size_t)BATCH * IN_FEAT];              // 64 MB intermediate h
__device__ float g_gthi[(size_t)NPAIRS_TOTAL * GT_PAIR];    // gates^T hi (tf32-exact)
__device__ float g_gtlo[(size_t)NPAIRS_TOTAL * GT_PAIR];    // gates^T lo residual

// ---------------- tf32 helpers ----------------
__device__ __forceinline__ uint32_t tf32_hi(float x) {
    uint32_t h; asm("cvt.rna.tf32.f32 %0, %1;" : "=r"(h) : "f"(x)); return h;
}
// D += A(tf32) * B(tf32), m16n8k8, A row-major, B col-major
__device__ __forceinline__ void mma8(float* d, const uint32_t* a, const uint32_t* b) {
    asm volatile(
        "mma.sync.aligned.m16n8k8.row.col.f32.tf32.tf32.f32 "
        "{%0,%1,%2,%3}, {%4,%5,%6,%7}, {%8,%9}, {%0,%1,%2,%3};"
        : "+f"(d[0]), "+f"(d[1]), "+f"(d[2]), "+f"(d[3])
        : "r"(a[0]), "r"(a[1]), "r"(a[2]), "r"(a[3]), "r"(b[0]), "r"(b[1]));
}

// ---------------- gate reduction: emit transposed hi/lo tiles ----------------
__device__ __forceinline__ void store_gt(int gb, int o, float s1, float s2) {
    float* dh = g_gthi + (size_t)gb * GT_PAIR;
    float* dl = g_gtlo + (size_t)gb * GT_PAIR;
    int ij = o >> 3, m = o & 7;
    float h1 = __uint_as_float(tf32_hi(s1));
    dh[m * GT_STRIDE + ij] = h1;  dl[m * GT_STRIDE + ij] = s1 - h1;
    float h2 = __uint_as_float(tf32_hi(s2));
    dh[(8 + m) * GT_STRIDE + ij] = h2;  dl[(8 + m) * GT_STRIDE + ij] = s2 - h2;
}

__device__ __forceinline__ void reduce_one_pair_256(int gb, const float* __restrict__ src,
                                                    float* __restrict__ sG)
{
    int tid = threadIdx.x;
    float acc[16];
#pragma unroll
    for (int t = 0; t < 16; t++) acc[t] = 0.f;
#pragma unroll
    for (int rc = 0; rc < 16; rc++) {
        const float* p = src + rc * 4096;
#pragma unroll
        for (int t = 0; t < 16; t++) acc[t] += p[t * 256 + tid];
    }
#pragma unroll
    for (int t = 0; t < 16; t++) sG[t * 256 + tid] = acc[t];
    __syncthreads();
#pragma unroll
    for (int u = 0; u < 2; u++) {
        int o = u * 256 + tid;          // 0..511
        float s1 = 0.f;
#pragma unroll
        for (int n = 0; n < 8; n++) s1 += sG[o * 8 + n];
        int ij = o >> 3, nn = o & 7;
        float s2 = 0.f;
#pragma unroll
        for (int m = 0; m < 8; m++) s2 += sG[ij * 64 + m * 8 + nn];
        store_gt(gb, o, s1, s2);
    }
}

__device__ __forceinline__ void reduce_one_pair_128(int gb, const float* __restrict__ src,
                                                    float* __restrict__ sG)
{
    int tid = threadIdx.x;
#pragma unroll 1
    for (int half = 0; half < 2; half++) {
        float acc[16];
#pragma unroll
        for (int t = 0; t < 16; t++) acc[t] = 0.f;
#pragma unroll 4
        for (int rc = 0; rc < 16; rc++) {
            const float* p = src + rc * 4096 + half * 2048;
#pragma unroll
            for (int t = 0; t < 16; t++) acc[t] += p[t * 128 + tid];
        }
#pragma unroll
        for (int t = 0; t < 16; t++) sG[half * 2048 + t * 128 + tid] = acc[t];
    }
    __syncthreads();
#pragma unroll
    for (int u = 0; u < 4; u++) {
        int o = u * 128 + tid;          // 0..511
        float s1 = 0.f;
#pragma unroll
        for (int n = 0; n < 8; n++) s1 += sG[o * 8 + n];
        int ij = o >> 3, nn = o & 7;
        float s2 = 0.f;
#pragma unroll
        for (int m = 0; m < 8; m++) s2 += sG[ij * 64 + m * 8 + nn];
        store_gt(gb, o, s1, s2);
    }
}

// ---------------- Prep kernel: gates0 reduction + permuted gather ----------------
__global__ __launch_bounds__(256) void prep_kernel(
    const float* __restrict__ g0,
    const float* __restrict__ x, const int* __restrict__ perm)
{
    __shared__ float sG[4096];
    if (blockIdx.x < 256) {
        reduce_one_pair_256(blockIdx.x, g0 + (size_t)blockIdx.x * 65536, sG);
        return;
    }
    int b = blockIdx.x - 256;
    const float* xr = x + (size_t)b * IN_FEAT;
    float* hr = g_h + (size_t)b * IN_FEAT;
    int tid = threadIdx.x;
#pragma unroll
    for (int c = 0; c < 16; c++) {
        int q = c * 256 + tid;
        hr[q] = xr[perm[q]];
    }
}

// ---------------- Layer kernel: tensor-core GEMM, latency-optimized ----------------
// R15 diagnosis: MMA path was dependency-bound -- 24 serially-dependent HMMA
// per iter per accumulator (3 split terms x 8 kc). Fixes here:
//  1. SPLIT ACCUMULATORS: separate chains for hi*hi / hi*lo / lo*hi, summed
//     in the epilogue -> chain length 8, six independent chains in flight.
//  2. TILE PIPELINE: prefetch iter it+1's coalesced LDG into registers during
//     iter it's MMAs; STS into alternating 320-float buffers (double buffer).
// Math identical to R13/R15 (validated): 3-term tf32 split mma m16n8k8.
template<int OFFSET, bool EPI, bool FUSE_REDUCE>
__global__ __launch_bounds__(128, 3) void layer_kernel(
    int gate_base,
    const float* __restrict__ g1r, const float* __restrict__ g2r,
    const float* __restrict__ alphap,
    const float* __restrict__ scale,
    const float* __restrict__ bias,
    float* __restrict__ out)
{
    __shared__ float sS[4096];   // 16KB: reduce area / 4 warps x 2 x 320-float buffers

    int kx = blockIdx.x;
    if (FUSE_REDUCE) {
        if (kx < 511) {
            if (blockIdx.y == 0) {
                int gb = 256 + kx;
                const float* src = (gb < 511) ? g1r + (size_t)(gb - 256) * 65536
                                              : g2r + (size_t)(gb - 511) * 65536;
                reduce_one_pair_128(gb, src, sS);
            }
            return;
        }
        kx -= 511;
    }
    const int k = kx;
    const int tid = threadIdx.x;
    const int w = tid >> 5, t = tid & 31;
    const int g = t >> 2, tg = t & 3;
    const size_t col = ((size_t)(OFFSET + 2 * k)) * 8;   // 16 contiguous h columns
    float* sW = sS + w * 640;                            // warp-private 2-buffer region

    // ---- B fragments for this pair: held in registers for the whole job ----
    const float* bh = g_gthi + (size_t)(gate_base + k) * GT_PAIR;
    const float* bl = g_gtlo + (size_t)(gate_base + k) * GT_PAIR;
    uint32_t bhi[2][8][2], blo[2][8][2];
#pragma unroll
    for (int nb = 0; nb < 2; nb++)
#pragma unroll
        for (int kc = 0; kc < 8; kc++) {
            int idx = (nb * 8 + g) * GT_STRIDE + kc * 8 + tg;
            bhi[nb][kc][0] = __float_as_uint(__ldg(bh + idx));
            bhi[nb][kc][1] = __float_as_uint(__ldg(bh + idx + 4));
            blo[nb][kc][0] = __float_as_uint(__ldg(bl + idx));
            blo[nb][kc][1] = __float_as_uint(__ldg(bl + idx + 4));
        }

    float al = 1.f;
    float sc[2][2], bi[2][2];
    if (EPI) {
        al = __ldg(alphap);
#pragma unroll
        for (int nb = 0; nb < 2; nb++)
#pragma unroll
            for (int e = 0; e < 2; e++) {
                size_t c = col + nb * 8 + 2 * tg + e;
                sc[nb][e] = __ldg(scale + c);
                bi[nb][e] = __ldg(bias + c);
            }
    }

    // ---- preload tile 0 into registers ----
    float4 va0, va1;
    {
        int rbase = blockIdx.y * 256 + w * 16;
        va0 = *(const float4*)(g_h + (size_t)(rbase + (t >> 2)) * IN_FEAT + col + (t & 3) * 4);
        va1 = *(const float4*)(g_h + (size_t)(rbase + (t >> 2) + 8) * IN_FEAT + col + (t & 3) * 4);
    }

#pragma unroll 1
    for (int it = 0; it < 4; it++) {
        int rbase = blockIdx.y * 256 + it * 64 + w * 16;
        float* buf = sW + (it & 1) * 320;

        __syncwarp();   // prior reads of this buffer (iter it-2) complete
        *(float4*)(buf + (t >> 2) * 20 + (t & 3) * 4)       = va0;
        *(float4*)(buf + ((t >> 2) + 8) * 20 + (t & 3) * 4) = va1;
        if (it < 3) {   // prefetch next tile while this iter computes
            int rb2 = rbase + 64;
            va0 = *(const float4*)(g_h + (size_t)(rb2 + (t >> 2)) * IN_FEAT + col + (t & 3) * 4);
            va1 = *(const float4*)(g_h + (size_t)(rb2 + (t >> 2) + 8) * IN_FEAT + col + (t & 3) * 4);
        }
        __syncwarp();

        // ---- fragment reads from SMEM ----
        float4 u0 = *(const float4*)(buf + g * 20);
        float4 u1 = *(const float4*)(buf + g * 20 + 4);
        float4 v0 = *(const float4*)(buf + (g + 8) * 20);
        float4 v1 = *(const float4*)(buf + (g + 8) * 20 + 4);
        float x1a[8] = {u0.x, u0.y, u0.z, u0.w, u1.x, u1.y, u1.z, u1.w};
        float x1b[8] = {v0.x, v0.y, v0.z, v0.w, v1.x, v1.y, v1.z, v1.w};
        float x2a0 = buf[g * 20 + 8 + tg],        x2a1 = buf[g * 20 + 12 + tg];
        float x2b0 = buf[(g + 8) * 20 + 8 + tg],  x2b1 = buf[(g + 8) * 20 + 12 + tg];

        // split accumulators: independent chains for hi*hi / hi*lo / lo*hi
        float d0a[4] = {0,0,0,0}, d0b[4] = {0,0,0,0}, d0c[4] = {0,0,0,0};
        float d1a[4] = {0,0,0,0}, d1b[4] = {0,0,0,0}, d1c[4] = {0,0,0,0};

#pragma unroll
        for (int kc = 0; kc < 8; kc++) {
            // A fragment (row-major m16k8): a0:(g,tg) a1:(g+8,tg) a2:(g,tg+4) a3:(g+8,tg+4)
            float av[4] = { x1a[kc] * x2a0, x1b[kc] * x2b0,
                            x1a[kc] * x2a1, x1b[kc] * x2b1 };
            uint32_t ah[4], alo_[4];
#pragma unroll
            for (int e = 0; e < 4; e++) {
                ah[e] = tf32_hi(av[e]);
                alo_[e] = __float_as_uint(av[e] - __uint_as_float(ah[e]));
            }
            mma8(d0a, ah,   bhi[0][kc]);
            mma8(d0b, ah,   blo[0][kc]);
            mma8(d0c, alo_, bhi[0][kc]);
            mma8(d1a, ah,   bhi[1][kc]);
            mma8(d1b, ah,   blo[1][kc]);
            mma8(d1c, alo_, bhi[1][kc]);
        }

        // D fragment: e0,e1 = row g cols 2tg,2tg+1 ; e2,e3 = row g+8 same cols
        int ra = rbase + g, rb = rbase + g + 8;
#pragma unroll
        for (int nb = 0; nb < 2; nb++) {
            float d[4];
#pragma unroll
            for (int e = 0; e < 4; e++)
                d[e] = nb ? (d1a[e] + d1b[e] + d1c[e]) : (d0a[e] + d0b[e] + d0c[e]);
            size_t ca = (size_t)ra * IN_FEAT + col + nb * 8 + 2 * tg;
            size_t cb = (size_t)rb * IN_FEAT + col + nb * 8 + 2 * tg;
            if (!EPI) {
                *(float2*)(g_h + ca) = make_float2(d[0], d[1]);
                *(float2*)(g_h + cb) = make_float2(d[2], d[3]);
            } else {
                *(float2*)(out + ca) = make_float2(al * d[0] * sc[nb][0] + bi[nb][0],
                                                   al * d[1] * sc[nb][1] + bi[nb][1]);
                *(float2*)(out + cb) = make_float2(al * d[2] * sc[nb][0] + bi[nb][0],
                                                   al * d[3] * sc[nb][1] + bi[nb][1]);
            }
        }
    }
}

// ---------------- launch ----------------
extern "C" void kernel_launch(void* const* d_in, const int* in_sizes, int n_in,
                              void* d_out, int out_size)
{
    (void)in_sizes; (void)n_in; (void)out_size;
    const float* x     = (const float*)d_in[0];
    const float* g0    = (const float*)d_in[1];
    const float* g1    = (const float*)d_in[2];
    const float* g2    = (const float*)d_in[3];
    const float* alpha = (const float*)d_in[4];
    const float* scale = (const float*)d_in[5];
    const float* bias  = (const float*)d_in[6];
    const int*   perm  = (const int*)d_in[7];
    float* out = (float*)d_out;

    // prep: gates0 reduce (256 blocks) + permuted gather (4096 blocks)
    prep_kernel<<<256 + BATCH, 256>>>(g0, x, perm);
    // layer 0: 511 leading reduce blocks (gates1+gates2) + 256 pair-blocks x 16 row-groups
    layer_kernel<0, false, true ><<<dim3(511 + 256, 16), 128>>>(0,   g1, g2, nullptr, nullptr, nullptr, nullptr);
    layer_kernel<1, false, false><<<dim3(255, 16),       128>>>(256, nullptr, nullptr, nullptr, nullptr, nullptr, nullptr);
    layer_kernel<0, true,  false><<<dim3(256, 16),       128>>>(511, nullptr, nullptr, alpha, scale, bias, out);
}

// round 17
// speedup vs baseline: 1.2712x; 1.2421x over previous
#include <cuda_runtime.h>
#include <cstdint>

#define BATCH    4096
#define IN_FEAT  4096
#define NPAIRS_TOTAL 767   // 256 + 255 + 256

typedef unsigned long long ull;

// ---------------- scratch (device globals; no allocation allowed) ----------------
__device__ float g_h[(size_t)BATCH * IN_FEAT];                 // 64 MB intermediate h
__device__ unsigned int g_gb0[(size_t)NPAIRS_TOTAL * 512];     // gate bf16 lvl0, u32 = j-pair
__device__ unsigned int g_gb1[(size_t)NPAIRS_TOTAL * 512];     // gate bf16 lvl1

// ---------------- helpers ----------------
__device__ __forceinline__ ull pack2(float c) {
    ull r; asm("mov.b64 %0, {%1, %1};" : "=l"(r) : "f"(c)); return r;
}
__device__ __forceinline__ ull mul2(ull a, ull b) {
    ull r; asm("mul.rn.f32x2 %0, %1, %2;" : "=l"(r) : "l"(a), "l"(b)); return r;
}
__device__ __forceinline__ float2 unpack2(ull v) {
    float2 f; asm("mov.b64 {%0, %1}, %2;" : "=f"(f.x), "=f"(f.y) : "l"(v)); return f;
}
__device__ __forceinline__ unsigned short bf16rn(float s) {
    unsigned short h; asm("cvt.rn.bf16.f32 %0, %1;" : "=h"(h) : "f"(s)); return h;
}
__device__ __forceinline__ float bf16tof(unsigned short h) {
    return __uint_as_float(((uint32_t)h) << 16);
}
__device__ __forceinline__ uint32_t bf16x2rn(float hi, float lo) {
    uint32_t d; asm("cvt.rn.bf16x2.f32 %0, %1, %2;" : "=r"(d) : "f"(hi), "f"(lo)); return d;
}
// D += A(bf16) * B(bf16), m16n8k16, A row-major, B col-major
__device__ __forceinline__ void mma16(float* d, uint32_t a0, uint32_t a1, uint32_t a2,
                                      uint32_t a3, uint32_t b0, uint32_t b1) {
    asm volatile(
        "mma.sync.aligned.m16n8k16.row.col.f32.bf16.bf16.f32 "
        "{%0,%1,%2,%3}, {%4,%5,%6,%7}, {%8,%9}, {%0,%1,%2,%3};"
        : "+f"(d[0]), "+f"(d[1]), "+f"(d[2]), "+f"(d[3])
        : "r"(a0), "r"(a1), "r"(a2), "r"(a3), "r"(b0), "r"(b1));
}

// ---------------- gate reduction: emit 2-level bf16 tiles ----------------
// storage (u16 index): ((i*2 + nb)*8 + m)*8 + j  -> u32 loads give (j, j+1) pairs
__device__ __forceinline__ void store_gt(int gb, int o, float s1, float s2) {
    int ij = o >> 3, m = o & 7, i = ij >> 3, j = ij & 7;
    unsigned short* d0 = (unsigned short*)(g_gb0 + (size_t)gb * 512);
    unsigned short* d1 = (unsigned short*)(g_gb1 + (size_t)gb * 512);
    int idx = ((i * 2 + 0) * 8 + m) * 8 + j;
    unsigned short h = bf16rn(s1);
    d0[idx] = h;  d1[idx] = bf16rn(s1 - bf16tof(h));
    idx = ((i * 2 + 1) * 8 + m) * 8 + j;
    h = bf16rn(s2);
    d0[idx] = h;  d1[idx] = bf16rn(s2 - bf16tof(h));
}

__device__ __forceinline__ void reduce_one_pair_256(int gb, const float* __restrict__ src,
                                                    float* __restrict__ sG)
{
    int tid = threadIdx.x;
    float acc[16];
#pragma unroll
    for (int t = 0; t < 16; t++) acc[t] = 0.f;
#pragma unroll
    for (int rc = 0; rc < 16; rc++) {
        const float* p = src + rc * 4096;
#pragma unroll
        for (int t = 0; t < 16; t++) acc[t] += p[t * 256 + tid];
    }
#pragma unroll
    for (int t = 0; t < 16; t++) sG[t * 256 + tid] = acc[t];
    __syncthreads();
#pragma unroll
    for (int u = 0; u < 2; u++) {
        int o = u * 256 + tid;          // 0..511
        float s1 = 0.f;
#pragma unroll
        for (int n = 0; n < 8; n++) s1 += sG[o * 8 + n];
        int ij = o >> 3, nn = o & 7;
        float s2 = 0.f;
#pragma unroll
        for (int m = 0; m < 8; m++) s2 += sG[ij * 64 + m * 8 + nn];
        store_gt(gb, o, s1, s2);
    }
}

__device__ __forceinline__ void reduce_one_pair_128(int gb, const float* __restrict__ src,
                                                    float* __restrict__ sG)
{
    int tid = threadIdx.x;
#pragma unroll 1
    for (int half = 0; half < 2; half++) {
        float acc[16];
#pragma unroll
        for (int t = 0; t < 16; t++) acc[t] = 0.f;
#pragma unroll 4
        for (int rc = 0; rc < 16; rc++) {
            const float* p = src + rc * 4096 + half * 2048;
#pragma unroll
            for (int t = 0; t < 16; t++) acc[t] += p[t * 128 + tid];
        }
#pragma unroll
        for (int t = 0; t < 16; t++) sG[half * 2048 + t * 128 + tid] = acc[t];
    }
    __syncthreads();
#pragma unroll
    for (int u = 0; u < 4; u++) {
        int o = u * 128 + tid;          // 0..511
        float s1 = 0.f;
#pragma unroll
        for (int n = 0; n < 8; n++) s1 += sG[o * 8 + n];
        int ij = o >> 3, nn = o & 7;
        float s2 = 0.f;
#pragma unroll
        for (int m = 0; m < 8; m++) s2 += sG[ij * 64 + m * 8 + nn];
        store_gt(gb, o, s1, s2);
    }
}

// ---------------- Prep kernel: gates0 reduction + permuted gather ----------------
__global__ __launch_bounds__(256) void prep_kernel(
    const float* __restrict__ g0,
    const float* __restrict__ x, const int* __restrict__ perm)
{
    __shared__ float sG[4096];
    if (blockIdx.x < 256) {
        reduce_one_pair_256(blockIdx.x, g0 + (size_t)blockIdx.x * 65536, sG);
        return;
    }
    int b = blockIdx.x - 256;
    const float* xr = x + (size_t)b * IN_FEAT;
    float* hr = g_h + (size_t)b * IN_FEAT;
    int tid = threadIdx.x;
#pragma unroll
    for (int c = 0; c < 16; c++) {
        int q = c * 256 + tid;
        hr[q] = xr[perm[q]];
    }
}

// ---------------- Layer kernel: 2x2 bf16-split tensor GEMM ----------------
// Replaces 3x tf32.k8 with 2x bf16.k16 per (kc, nb): products and gates each
// split into two rn-bf16 levels; MMA1 = Sum p0g0+p1g1, MMA2 (B regs swapped,
// zero extra storage) = Sum p0g1+p1g0 -> together Sum (p0+p1)(g0+g1).
// Residuals <= 2^-16 per factor -> ~1e-4 rel after 3 layers (budget 1e-3).
// Tensor instr/iter 48 -> 32; B-frag regs 64 -> 32 -> 4 CTAs/SM.
// Keeps R16's double-buffered coalesced tile pipeline + split accumulators.
template<int OFFSET, bool EPI, bool FUSE_REDUCE>
__global__ __launch_bounds__(128, 4) void layer_kernel(
    int gate_base,
    const float* __restrict__ g1r, const float* __restrict__ g2r,
    const float* __restrict__ alphap,
    const float* __restrict__ scale,
    const float* __restrict__ bias,
    float* __restrict__ out)
{
    __shared__ float sS[4096];   // 16KB: reduce area / 4 warps x 2 x 320-float buffers

    int kx = blockIdx.x;
    if (FUSE_REDUCE) {
        if (kx < 511) {
            if (blockIdx.y == 0) {
                int gb = 256 + kx;
                const float* src = (gb < 511) ? g1r + (size_t)(gb - 256) * 65536
                                              : g2r + (size_t)(gb - 511) * 65536;
                reduce_one_pair_128(gb, src, sS);
            }
            return;
        }
        kx -= 511;
    }
    const int k = kx;
    const int tid = threadIdx.x;
    const int w = tid >> 5, t = tid & 31;
    const int g = t >> 2, tg = t & 3;
    const size_t col = ((size_t)(OFFSET + 2 * k)) * 8;   // 16 contiguous h columns
    float* sW = sS + w * 640;                            // warp-private 2-buffer region

    // ---- B fragments (bf16 level pairs), held in registers for the whole job ----
    const unsigned int* pb0 = g_gb0 + (size_t)(gate_base + k) * 512;
    const unsigned int* pb1 = g_gb1 + (size_t)(gate_base + k) * 512;
    uint32_t bl0[8][2], bl1[8][2];
#pragma unroll
    for (int kc = 0; kc < 8; kc++)
#pragma unroll
        for (int nb = 0; nb < 2; nb++) {
            int idx = ((kc * 2 + nb) * 8 + g) * 4 + tg;
            bl0[kc][nb] = __ldg(pb0 + idx);
            bl1[kc][nb] = __ldg(pb1 + idx);
        }

    float al = 1.f;
    float sc[2][2], bi[2][2];
    if (EPI) {
        al = __ldg(alphap);
#pragma unroll
        for (int nb = 0; nb < 2; nb++)
#pragma unroll
            for (int e = 0; e < 2; e++) {
                size_t c = col + nb * 8 + 2 * tg + e;
                sc[nb][e] = __ldg(scale + c);
                bi[nb][e] = __ldg(bias + c);
            }
    }

    // ---- preload tile 0 into registers ----
    float4 va0, va1;
    {
        int rbase = blockIdx.y * 256 + w * 16;
        va0 = *(const float4*)(g_h + (size_t)(rbase + (t >> 2)) * IN_FEAT + col + (t & 3) * 4);
        va1 = *(const float4*)(g_h + (size_t)(rbase + (t >> 2) + 8) * IN_FEAT + col + (t & 3) * 4);
    }

#pragma unroll 1
    for (int it = 0; it < 4; it++) {
        int rbase = blockIdx.y * 256 + it * 64 + w * 16;
        float* buf = sW + (it & 1) * 320;

        __syncwarp();   // prior reads of this buffer (iter it-2) complete
        *(float4*)(buf + (t >> 2) * 20 + (t & 3) * 4)       = va0;
        *(float4*)(buf + ((t >> 2) + 8) * 20 + (t & 3) * 4) = va1;
        if (it < 3) {   // prefetch next tile while this iter computes
            int rb2 = rbase + 64;
            va0 = *(const float4*)(g_h + (size_t)(rb2 + (t >> 2)) * IN_FEAT + col + (t & 3) * 4);
            va1 = *(const float4*)(g_h + (size_t)(rb2 + (t >> 2) + 8) * IN_FEAT + col + (t & 3) * 4);
        }
        __syncwarp();

        // ---- fragment reads from SMEM ----
        float4 u0 = *(const float4*)(buf + g * 20);
        float4 u1 = *(const float4*)(buf + g * 20 + 4);
        float4 v0 = *(const float4*)(buf + (g + 8) * 20);
        float4 v1 = *(const float4*)(buf + (g + 8) * 20 + 4);
        float x1a[8] = {u0.x, u0.y, u0.z, u0.w, u1.x, u1.y, u1.z, u1.w};
        float x1b[8] = {v0.x, v0.y, v0.z, v0.w, v1.x, v1.y, v1.z, v1.w};
        // x2 pairs at j = 2tg, 2tg+1 (8B-aligned LDS.64)
        ull x2pa = *(const ull*)(buf + g * 20 + 8 + 2 * tg);
        ull x2pb = *(const ull*)(buf + (g + 8) * 20 + 8 + 2 * tg);

        // split accumulators: two independent MMA streams per nb
        float dA0[4] = {0,0,0,0}, dB0[4] = {0,0,0,0};
        float dA1[4] = {0,0,0,0}, dB1[4] = {0,0,0,0};

#pragma unroll
        for (int kc = 0; kc < 8; kc++) {
            ull ava = mul2(pack2(x1a[kc]), x2pa);     // products row g, j=2tg,2tg+1
            ull avb = mul2(pack2(x1b[kc]), x2pb);     // row g+8
            float2 fa = unpack2(ava), fb = unpack2(avb);
            uint32_t p0a = bf16x2rn(fa.y, fa.x);      // lvl0 pair (lo = j=2tg)
            uint32_t p0b = bf16x2rn(fb.y, fb.x);
            float ra0 = fa.x - __uint_as_float(p0a << 16);
            float ra1 = fa.y - __uint_as_float(p0a & 0xFFFF0000u);
            float rb0 = fb.x - __uint_as_float(p0b << 16);
            float rb1 = fb.y - __uint_as_float(p0b & 0xFFFF0000u);
            uint32_t p1a = bf16x2rn(ra1, ra0);        // lvl1 pair
            uint32_t p1b = bf16x2rn(rb1, rb0);
            // MMA1: p0*g0 + p1*g1 ; MMA2 (B swapped): p0*g1 + p1*g0
            mma16(dA0, p0a, p0b, p1a, p1b, bl0[kc][0], bl1[kc][0]);
            mma16(dB0, p0a, p0b, p1a, p1b, bl1[kc][0], bl0[kc][0]);
            mma16(dA1, p0a, p0b, p1a, p1b, bl0[kc][1], bl1[kc][1]);
            mma16(dB1, p0a, p0b, p1a, p1b, bl1[kc][1], bl0[kc][1]);
        }

        // D fragment: e0,e1 = row g cols 2tg,2tg+1 ; e2,e3 = row g+8 same cols
        int ra = rbase + g, rb = rbase + g + 8;
#pragma unroll
        for (int nb = 0; nb < 2; nb++) {
            float d[4];
#pragma unroll
            for (int e = 0; e < 4; e++)
                d[e] = nb ? (dA1[e] + dB1[e]) : (dA0[e] + dB0[e]);
            size_t ca = (size_t)ra * IN_FEAT + col + nb * 8 + 2 * tg;
            size_t cb = (size_t)rb * IN_FEAT + col + nb * 8 + 2 * tg;
            if (!EPI) {
                *(float2*)(g_h + ca) = make_float2(d[0], d[1]);
                *(float2*)(g_h + cb) = make_float2(d[2], d[3]);
            } else {
                *(float2*)(out + ca) = make_float2(al * d[0] * sc[nb][0] + bi[nb][0],
                                                   al * d[1] * sc[nb][1] + bi[nb][1]);
                *(float2*)(out + cb) = make_float2(al * d[2] * sc[nb][0] + bi[nb][0],
                                                   al * d[3] * sc[nb][1] + bi[nb][1]);
            }
        }
    }
}

// ---------------- launch ----------------
extern "C" void kernel_launch(void* const* d_in, const int* in_sizes, int n_in,
                              void* d_out, int out_size)
{
    (void)in_sizes; (void)n_in; (void)out_size;
    const float* x     = (const float*)d_in[0];
    const float* g0    = (const float*)d_in[1];
    const float* g1    = (const float*)d_in[2];
    const float* g2    = (const float*)d_in[3];
    const float* alpha = (const float*)d_in[4];
    const float* scale = (const float*)d_in[5];
    const float* bias  = (const float*)d_in[6];
    const int*   perm  = (const int*)d_in[7];
    float* out = (float*)d_out;

    // prep: gates0 reduce (256 blocks) + permuted gather (4096 blocks)
    prep_kernel<<<256 + BATCH, 256>>>(g0, x, perm);
    // layer 0: 511 leading reduce blocks (gates1+gates2) + 256 pair-blocks x 16 row-groups
    layer_kernel<0, false, true ><<<dim3(511 + 256, 16), 128>>>(0,   g1, g2, nullptr, nullptr, nullptr, nullptr);
    layer_kernel<1, false, false><<<dim3(255, 16),       128>>>(256, nullptr, nullptr, nullptr, nullptr, nullptr, nullptr);
    layer_kernel<0, true,  false><<<dim3(256, 16),       128>>>(511, nullptr, nullptr, alpha, scale, bias, out);
}